// round 5
// baseline (speedup 1.0000x reference)
#include <cuda_runtime.h>
#include <cstdint>
#include <math.h>

#define DEV_INLINE __device__ __forceinline__

// ---------------- problem constants ----------------
constexpr int B_    = 65536;
constexpr int SEQ_  = 2;
constexpr int P_    = 1009;
constexpr int D_    = 256;
constexpr int H_    = 4;
constexpr int DH_   = 64;
constexpr int HID_  = 1024;
constexpr int M_    = B_ * SEQ_;   // 131072 rows
constexpr int NPAD_ = 1024;        // padded unembed N

// ---------------- scratch (static device globals; allocation-free rule) ----------------
__device__ __align__(16) float g_qkv [SEQ_ * P_ * 3 * D_];      // [(s*P+p)*768 + t*256 + he]
__device__ __align__(16) float g_M1T [HID_ * D_];               // (W_O @ fc1^T)^T : [j][he]
__device__ __align__(16) float g_b1  [HID_];                    // b_O @ fc1^T + fc1_b
__device__ __align__(16) float g_fc2r[D_ * HID_];               // tf32-rounded fc2_w
__device__ __align__(16) float g_unw [NPAD_ * D_];              // tf32-rounded, zero-padded un_w
__device__ __align__(16) float g_unb [NPAD_];
__device__ __align__(16) float g_z    [(size_t)M_ * D_];        // attention output (tf32-rounded)
__device__ __align__(16) float g_hid  [(size_t)M_ * HID_];      // relu MLP hidden (tf32-rounded)
__device__ __align__(16) float g_resid[(size_t)M_ * D_];        // fc2 output (tf32-rounded)

// ---------------- helpers ----------------
DEV_INLINE float rtf32(float x) {
    uint32_t u;
    asm volatile("cvt.rna.tf32.f32 %0, %1;" : "=r"(u) : "f"(x));
    return __uint_as_float(u);
}

DEV_INLINE float warpSum(float v) {
    #pragma unroll
    for (int off = 16; off; off >>= 1) v += __shfl_xor_sync(0xffffffffu, v, off);
    return v;
}

DEV_INLINE void cpa16(float* dst, const float* src) {
    uint32_t s = (uint32_t)__cvta_generic_to_shared(dst);
    asm volatile("cp.async.cg.shared.global [%0], [%1], 16;" :: "r"(s), "l"(src));
}
DEV_INLINE void cpa_commit() { asm volatile("cp.async.commit_group;"); }
template<int N> DEV_INLINE void cpa_wait() { asm volatile("cp.async.wait_group %0;" :: "n"(N)); }

// m16n8k8 tf32 mma, fp32 accumulate (operands pre-rounded to tf32 -> truncation exact)
DEV_INLINE void mma8(float* c, const uint32_t* a, uint32_t b0, uint32_t b1) {
    asm volatile(
        "mma.sync.aligned.m16n8k8.row.col.f32.tf32.tf32.f32 "
        "{%0,%1,%2,%3},{%4,%5,%6,%7},{%8,%9},{%0,%1,%2,%3};"
        : "+f"(c[0]), "+f"(c[1]), "+f"(c[2]), "+f"(c[3])
        : "r"(a[0]), "r"(a[1]), "r"(a[2]), "r"(a[3]), "r"(b0), "r"(b1));
}

// ---------------- PK1: QKV table for all 2018 (pos, token) rows ----------------
__global__ void pk_qkv(const float* __restrict__ tok, const float* __restrict__ pos,
                       const float* __restrict__ WQ, const float* __restrict__ WK,
                       const float* __restrict__ WV, const float* __restrict__ bQ,
                       const float* __restrict__ bK, const float* __restrict__ bV) {
    __shared__ float hv[8][D_];
    int t   = threadIdx.x;                  // 0..255 == he
    int sp0 = blockIdx.x * 8;
    #pragma unroll
    for (int r = 0; r < 8; r++) {
        int sp = sp0 + r;
        if (sp < SEQ_ * P_) {
            int s = sp / P_, p = sp % P_;
            hv[r][t] = tok[p * D_ + t] + pos[s * D_ + t];
        } else hv[r][t] = 0.f;
    }
    __syncthreads();
    int h = t >> 6, e = t & 63;
    const float* wq = WQ + h * D_ * DH_ + e;
    const float* wk = WK + h * D_ * DH_ + e;
    const float* wv = WV + h * D_ * DH_ + e;
    float aq[8] = {}, ak[8] = {}, av[8] = {};
    for (int d = 0; d < D_; d++) {
        float q = wq[d * DH_], k = wk[d * DH_], v = wv[d * DH_];
        #pragma unroll
        for (int r = 0; r < 8; r++) {
            float hd = hv[r][d];
            aq[r] += q * hd; ak[r] += k * hd; av[r] += v * hd;
        }
    }
    float bq = bQ[t], bk = bK[t], bv = bV[t];
    #pragma unroll
    for (int r = 0; r < 8; r++) {
        int sp = sp0 + r;
        if (sp < SEQ_ * P_) {
            float* o = g_qkv + (size_t)sp * (3 * D_);
            o[t] = aq[r] + bq; o[256 + t] = ak[r] + bk; o[512 + t] = av[r] + bv;
        }
    }
}

// ---------------- PK2: M1T[j][he] = sum_d W_O[he][d] * fc1_w[j][d] ----------------
__global__ void pk_m1(const float* __restrict__ WO, const float* __restrict__ fc1w) {
    __shared__ float sf[4][D_];
    int t  = threadIdx.x;           // = he row of W_O (flat [256][256])
    int j0 = blockIdx.x * 4;
    #pragma unroll
    for (int r = 0; r < 4; r++) sf[r][t] = fc1w[(j0 + r) * D_ + t];
    __syncthreads();
    const float* w = WO + t * D_;
    float acc[4] = {};
    for (int d = 0; d < D_; d++) {
        float wd = w[d];
        #pragma unroll
        for (int r = 0; r < 4; r++) acc[r] += wd * sf[r][d];
    }
    #pragma unroll
    for (int r = 0; r < 4; r++) g_M1T[(j0 + r) * D_ + t] = rtf32(acc[r]);
}

// ---------------- PKb: b1 = b_O @ fc1^T + fc1_b ----------------
__global__ void pk_b1(const float* __restrict__ bO, const float* __restrict__ fc1w,
                      const float* __restrict__ fc1b) {
    int j = blockIdx.x * blockDim.x + threadIdx.x;   // 0..1023
    float acc = fc1b[j];
    for (int d = 0; d < D_; d++) acc += bO[d] * fc1w[j * D_ + d];
    g_b1[j] = acc;
}

// ---------------- PKc: rounded/padded copies of un_w, un_b, fc2_w ----------------
__global__ void pk_copy(const float* __restrict__ unw, const float* __restrict__ unb,
                        const float* __restrict__ fc2w) {
    int gi = blockIdx.x * blockDim.x + threadIdx.x;  // 0..262143
    int p  = gi >> 8;
    g_unw[gi]  = (p < P_) ? rtf32(unw[gi]) : 0.f;
    g_fc2r[gi] = rtf32(fc2w[gi]);
    if (gi < NPAD_) g_unb[gi] = (gi < P_) ? unb[gi] : 0.f;
}

// ---------------- attention: gather qkv table, blended softmax over 2 keys ----------------
__global__ void attn_k(const int* __restrict__ x) {
    int warp = blockIdx.x * 8 + (threadIdx.x >> 5);
    int lane = threadIdx.x & 31;
    if (warp >= B_) return;
    int x0 = x[warp * 2 + 0];
    int x1 = x[warp * 2 + 1];
    const float* base0 = g_qkv + (size_t)x0 * (3 * D_);          // pos 0 row
    const float* base1 = g_qkv + (size_t)(P_ + x1) * (3 * D_);   // pos 1 row

    float s00[H_], s01[H_], s10[H_], s11[H_];
    #pragma unroll
    for (int h = 0; h < H_; h++) {
        int idx = h * DH_ + lane * 2;
        float2 q0 = *reinterpret_cast<const float2*>(base0 + idx);
        float2 k0 = *reinterpret_cast<const float2*>(base0 + 256 + idx);
        float2 q1 = *reinterpret_cast<const float2*>(base1 + idx);
        float2 k1 = *reinterpret_cast<const float2*>(base1 + 256 + idx);
        s00[h] = warpSum(q0.x * k0.x + q0.y * k0.y);
        s01[h] = warpSum(q0.x * k1.x + q0.y * k1.y);
        s10[h] = warpSum(q1.x * k0.x + q1.y * k0.y);
        s11[h] = warpSum(q1.x * k1.x + q1.y * k1.y);
    }

    float* z0row = g_z + (size_t)(warp * 2 + 0) * D_;
    float* z1row = g_z + (size_t)(warp * 2 + 1) * D_;
    const float scale = 0.125f;   // 1/sqrt(64)
    #pragma unroll
    for (int h = 0; h < H_; h++) {
        float a00 = s00[h] * scale, a01 = s01[h] * scale;
        float a10 = s10[h] * scale, a11 = s11[h] * scale;
        float m0 = fmaxf(a00, a01);
        float e00 = expf(a00 - m0), e01 = expf(a01 - m0);
        float r0 = 1.f / (e00 + e01);
        float p00 = 0.5f + 0.5f * e00 * r0;
        float p01 = 0.5f + 0.5f * e01 * r0;
        float m1 = fmaxf(a10, a11);
        float e10 = expf(a10 - m1), e11 = expf(a11 - m1);
        float r1 = 1.f / (e10 + e11);
        float p10 = 0.5f + 0.5f * e10 * r1;
        float p11 = 0.5f + 0.5f * e11 * r1;

        int idx = h * DH_ + lane * 2;
        float2 v0 = *reinterpret_cast<const float2*>(base0 + 512 + idx);
        float2 v1 = *reinterpret_cast<const float2*>(base1 + 512 + idx);
        float2 z0 = make_float2(rtf32(p00 * v0.x + p01 * v1.x), rtf32(p00 * v0.y + p01 * v1.y));
        float2 z1 = make_float2(rtf32(p10 * v0.x + p11 * v1.x), rtf32(p10 * v0.y + p11 * v1.y));
        *reinterpret_cast<float2*>(z0row + idx) = z0;
        *reinterpret_cast<float2*>(z1row + idx) = z1;
    }
}

// ---------------- tf32 GEMM: C[M x N] = A[M x K] * B[N x K]^T + bias ----------------
// STAGE 0: hid   = relu(z @ M1 + b1)        M=131072 K=256  N=1024
// STAGE 1: resid = hid @ fc2^T + fc2_b      M=131072 K=1024 N=256
// STAGE 2: out   = resid @ un_w^T + un_b    M=131072 K=256  N=1009 (padded 1024)
constexpr int BM = 128, BN = 128, BK = 32, LDT = BK + 4;   // +4 pad: conflict-free, 16B rows
constexpr int TILE_F = BM * LDT;                           // 4608 floats per tile buffer

template<int STAGE>
__global__ __launch_bounds__(256) void gemm_k(const float* __restrict__ extBias,
                                              float* __restrict__ extOut) {
    constexpr int K   = (STAGE == 1) ? 1024 : 256;
    constexpr int KT  = K / BK;
    constexpr int NLD = (STAGE == 0) ? 1024 : (STAGE == 1) ? 256 : 1009;

    const float* Ag; const float* Bg; const float* bias; float* C;
    if      (STAGE == 0) { Ag = g_z;     Bg = g_M1T;  bias = g_b1;    C = g_hid;   }
    else if (STAGE == 1) { Ag = g_hid;   Bg = g_fc2r; bias = extBias; C = g_resid; }
    else                 { Ag = g_resid; Bg = g_unw;  bias = g_unb;   C = extOut;  }

    extern __shared__ float sm[];
    float* As = sm;                 // 2 buffers
    float* Bs = sm + 2 * TILE_F;    // 2 buffers

    int t     = threadIdx.x;
    int mbase = blockIdx.y * BM;
    int nbase = blockIdx.x * BN;

    auto load_tiles = [&](int buf, int k0) {
        #pragma unroll
        for (int i = 0; i < 4; i++) {
            int idx = t + i * 256;
            int row = idx >> 3;
            int c4  = (idx & 7) << 2;
            cpa16(As + buf * TILE_F + row * LDT + c4, Ag + (size_t)(mbase + row) * K + k0 + c4);
            cpa16(Bs + buf * TILE_F + row * LDT + c4, Bg + (size_t)(nbase + row) * K + k0 + c4);
        }
        cpa_commit();
    };

    load_tiles(0, 0);

    int wid = t >> 5, lane = t & 31;
    int wm = wid & 3, wn = wid >> 2;     // 4x2 warp grid: warp tile 32(M) x 64(N)
    int lq = lane >> 2, lr = lane & 3;

    float acc[2][8][4];
    #pragma unroll
    for (int i = 0; i < 2; i++)
        #pragma unroll
        for (int j = 0; j < 8; j++)
            #pragma unroll
            for (int r = 0; r < 4; r++) acc[i][j][r] = 0.f;

    for (int kt = 0; kt < KT; kt++) {
        if (kt + 1 < KT) { load_tiles((kt + 1) & 1, (kt + 1) * BK); cpa_wait<1>(); }
        else             { cpa_wait<0>(); }
        __syncthreads();
        const float* Ab = As + (kt & 1) * TILE_F;
        const float* Bb = Bs + (kt & 1) * TILE_F;
        #pragma unroll
        for (int ks = 0; ks < BK / 8; ks++) {
            int k0 = ks * 8 + lr;
            uint32_t afr[2][4];
            #pragma unroll
            for (int mt = 0; mt < 2; mt++) {
                int r0 = wm * 32 + mt * 16 + lq;
                afr[mt][0] = __float_as_uint(Ab[r0 * LDT + k0]);
                afr[mt][1] = __float_as_uint(Ab[(r0 + 8) * LDT + k0]);
                afr[mt][2] = __float_as_uint(Ab[r0 * LDT + k0 + 4]);
                afr[mt][3] = __float_as_uint(Ab[(r0 + 8) * LDT + k0 + 4]);
            }
            #pragma unroll
            for (int nt = 0; nt < 8; nt++) {
                int n0 = wn * 64 + nt * 8 + lq;
                uint32_t b0 = __float_as_uint(Bb[n0 * LDT + k0]);
                uint32_t b1 = __float_as_uint(Bb[n0 * LDT + k0 + 4]);
                mma8(acc[0][nt], afr[0], b0, b1);
                mma8(acc[1][nt], afr[1], b0, b1);
            }
        }
        __syncthreads();
    }

    // epilogue
    #pragma unroll
    for (int mt = 0; mt < 2; mt++) {
        int row = mbase + wm * 32 + mt * 16 + lq;
        #pragma unroll
        for (int nt = 0; nt < 8; nt++) {
            int col = nbase + wn * 64 + nt * 8 + lr * 2;
            float bb0 = bias[col], bb1 = bias[col + 1];
            float v00 = acc[mt][nt][0] + bb0;
            float v01 = acc[mt][nt][1] + bb1;
            float v10 = acc[mt][nt][2] + bb0;
            float v11 = acc[mt][nt][3] + bb1;
            if (STAGE == 0) {
                v00 = fmaxf(v00, 0.f); v01 = fmaxf(v01, 0.f);
                v10 = fmaxf(v10, 0.f); v11 = fmaxf(v11, 0.f);
            }
            if (STAGE != 2) {
                v00 = rtf32(v00); v01 = rtf32(v01);
                v10 = rtf32(v10); v11 = rtf32(v11);
            }
            if (STAGE == 2) {
                size_t o0 = (size_t)row * NLD + col;
                size_t o1 = (size_t)(row + 8) * NLD + col;
                if (col < P_)     { C[o0]     = v00; C[o1]     = v10; }
                if (col + 1 < P_) { C[o0 + 1] = v01; C[o1 + 1] = v11; }
            } else {
                *reinterpret_cast<float2*>(C + (size_t)row * NLD + col)       = make_float2(v00, v01);
                *reinterpret_cast<float2*>(C + (size_t)(row + 8) * NLD + col) = make_float2(v10, v11);
            }
        }
    }
}

// ---------------- launcher ----------------
extern "C" void kernel_launch(void* const* d_in, const int* in_sizes, int n_in,
                              void* d_out, int out_size) {
    const int*   x    = (const int*)d_in[0];
    const float* tok  = (const float*)d_in[1];
    const float* pos  = (const float*)d_in[2];
    const float* WQ   = (const float*)d_in[3];
    const float* WK   = (const float*)d_in[4];
    const float* WV   = (const float*)d_in[5];
    const float* WO   = (const float*)d_in[6];
    const float* bQ   = (const float*)d_in[7];
    const float* bK   = (const float*)d_in[8];
    const float* bV   = (const float*)d_in[9];
    const float* bO   = (const float*)d_in[10];
    const float* fc1w = (const float*)d_in[11];
    const float* fc1b = (const float*)d_in[12];
    const float* fc2w = (const float*)d_in[13];
    const float* fc2b = (const float*)d_in[14];
    const float* unw  = (const float*)d_in[15];
    const float* unb  = (const float*)d_in[16];
    float* out = (float*)d_out;

    const int smem = 4 * TILE_F * (int)sizeof(float);   // 73728 B
    cudaFuncSetAttribute(gemm_k<0>, cudaFuncAttributeMaxDynamicSharedMemorySize, smem);
    cudaFuncSetAttribute(gemm_k<1>, cudaFuncAttributeMaxDynamicSharedMemorySize, smem);
    cudaFuncSetAttribute(gemm_k<2>, cudaFuncAttributeMaxDynamicSharedMemorySize, smem);

    pk_qkv <<<253,  256>>>(tok, pos, WQ, WK, WV, bQ, bK, bV);
    pk_m1  <<<256,  256>>>(WO, fc1w);
    pk_b1  <<<4,    256>>>(bO, fc1w, fc1b);
    pk_copy<<<1024, 256>>>(unw, unb, fc2w);
    attn_k <<<8192, 256>>>(x);

    gemm_k<0><<<dim3(8, 1024), 256, smem>>>(nullptr, nullptr);   // z -> hid
    gemm_k<1><<<dim3(2, 1024), 256, smem>>>(fc2b,    nullptr);   // hid -> resid
    gemm_k<2><<<dim3(8, 1024), 256, smem>>>(nullptr, out);       // resid -> logits
}

// round 8
// speedup vs baseline: 1.0169x; 1.0169x over previous
#include <cuda_runtime.h>
#include <cstdint>
#include <math.h>

#define DEV_INLINE __device__ __forceinline__

// ---------------- problem constants ----------------
constexpr int B_    = 65536;
constexpr int SEQ_  = 2;
constexpr int P_    = 1009;
constexpr int D_    = 256;
constexpr int H_    = 4;
constexpr int DH_   = 64;
constexpr int HID_  = 1024;
constexpr int M_    = B_ * SEQ_;   // 131072 rows
constexpr int NPAD_ = 1024;        // padded unembed N

// ---------------- scratch (static device globals; allocation-free rule) ----------------
__device__ __align__(16) float g_qkv [SEQ_ * P_ * 3 * D_];      // [(s*P+p)*768 + t*256 + he]
__device__ __align__(16) float g_M1T [HID_ * D_];               // (W_O @ fc1^T)^T : [j][he]
__device__ __align__(16) float g_b1  [HID_];                    // b_O @ fc1^T + fc1_b
__device__ __align__(16) float g_fc2r[D_ * HID_];               // tf32-rounded fc2_w
__device__ __align__(16) float g_unw [NPAD_ * D_];              // tf32-rounded, zero-padded un_w
__device__ __align__(16) float g_unb [NPAD_];
__device__ __align__(16) float g_z    [(size_t)M_ * D_];        // attention output (tf32-rounded)
__device__ __align__(16) float g_hid  [(size_t)M_ * HID_];      // relu MLP hidden (tf32-rounded)
__device__ __align__(16) float g_resid[(size_t)M_ * D_];        // fc2 output (tf32-rounded)

// ---------------- helpers ----------------
DEV_INLINE float rtf32(float x) {
    uint32_t u;
    asm volatile("cvt.rna.tf32.f32 %0, %1;" : "=r"(u) : "f"(x));
    return __uint_as_float(u);
}

DEV_INLINE float warpSum(float v) {
    #pragma unroll
    for (int off = 16; off; off >>= 1) v += __shfl_xor_sync(0xffffffffu, v, off);
    return v;
}

DEV_INLINE void cpa16(float* dst, const float* src) {
    uint32_t s = (uint32_t)__cvta_generic_to_shared(dst);
    asm volatile("cp.async.cg.shared.global [%0], [%1], 16;" :: "r"(s), "l"(src));
}
DEV_INLINE void cpa_commit() { asm volatile("cp.async.commit_group;"); }
template<int N> DEV_INLINE void cpa_wait() { asm volatile("cp.async.wait_group %0;" :: "n"(N)); }

// m16n8k8 tf32 mma, fp32 accumulate (operands pre-rounded to tf32 -> truncation exact)
DEV_INLINE void mma8(float* c, const uint32_t* a, uint32_t b0, uint32_t b1) {
    asm volatile(
        "mma.sync.aligned.m16n8k8.row.col.f32.tf32.tf32.f32 "
        "{%0,%1,%2,%3},{%4,%5,%6,%7},{%8,%9},{%0,%1,%2,%3};"
        : "+f"(c[0]), "+f"(c[1]), "+f"(c[2]), "+f"(c[3])
        : "r"(a[0]), "r"(a[1]), "r"(a[2]), "r"(a[3]), "r"(b0), "r"(b1));
}

// ---------------- PK1: QKV table for all 2018 (pos, token) rows ----------------
__global__ void pk_qkv(const float* __restrict__ tok, const float* __restrict__ pos,
                       const float* __restrict__ WQ, const float* __restrict__ WK,
                       const float* __restrict__ WV, const float* __restrict__ bQ,
                       const float* __restrict__ bK, const float* __restrict__ bV) {
    __shared__ float hv[8][D_];
    int t   = threadIdx.x;                  // 0..255 == he
    int sp0 = blockIdx.x * 8;
    #pragma unroll
    for (int r = 0; r < 8; r++) {
        int sp = sp0 + r;
        if (sp < SEQ_ * P_) {
            int s = sp / P_, p = sp % P_;
            hv[r][t] = tok[p * D_ + t] + pos[s * D_ + t];
        } else hv[r][t] = 0.f;
    }
    __syncthreads();
    int h = t >> 6, e = t & 63;
    const float* wq = WQ + h * D_ * DH_ + e;
    const float* wk = WK + h * D_ * DH_ + e;
    const float* wv = WV + h * D_ * DH_ + e;
    float aq[8] = {}, ak[8] = {}, av[8] = {};
    for (int d = 0; d < D_; d++) {
        float q = wq[d * DH_], k = wk[d * DH_], v = wv[d * DH_];
        #pragma unroll
        for (int r = 0; r < 8; r++) {
            float hd = hv[r][d];
            aq[r] += q * hd; ak[r] += k * hd; av[r] += v * hd;
        }
    }
    float bq = bQ[t], bk = bK[t], bv = bV[t];
    #pragma unroll
    for (int r = 0; r < 8; r++) {
        int sp = sp0 + r;
        if (sp < SEQ_ * P_) {
            float* o = g_qkv + (size_t)sp * (3 * D_);
            o[t] = aq[r] + bq; o[256 + t] = ak[r] + bk; o[512 + t] = av[r] + bv;
        }
    }
}

// ---------------- PK2: M1T[j][he] = sum_d W_O[he][d] * fc1_w[j][d] ----------------
__global__ void pk_m1(const float* __restrict__ WO, const float* __restrict__ fc1w) {
    __shared__ float sf[4][D_];
    int t  = threadIdx.x;           // = he row of W_O (flat [256][256])
    int j0 = blockIdx.x * 4;
    #pragma unroll
    for (int r = 0; r < 4; r++) sf[r][t] = fc1w[(j0 + r) * D_ + t];
    __syncthreads();
    const float* w = WO + t * D_;
    float acc[4] = {};
    for (int d = 0; d < D_; d++) {
        float wd = w[d];
        #pragma unroll
        for (int r = 0; r < 4; r++) acc[r] += wd * sf[r][d];
    }
    #pragma unroll
    for (int r = 0; r < 4; r++) g_M1T[(j0 + r) * D_ + t] = rtf32(acc[r]);
}

// ---------------- PKb: b1 = b_O @ fc1^T + fc1_b ----------------
__global__ void pk_b1(const float* __restrict__ bO, const float* __restrict__ fc1w,
                      const float* __restrict__ fc1b) {
    int j = blockIdx.x * blockDim.x + threadIdx.x;   // 0..1023
    float acc = fc1b[j];
    for (int d = 0; d < D_; d++) acc += bO[d] * fc1w[j * D_ + d];
    g_b1[j] = acc;
}

// ---------------- PKc: rounded/padded copies of un_w, un_b, fc2_w ----------------
__global__ void pk_copy(const float* __restrict__ unw, const float* __restrict__ unb,
                        const float* __restrict__ fc2w) {
    int gi = blockIdx.x * blockDim.x + threadIdx.x;  // 0..262143
    int p  = gi >> 8;
    g_unw[gi]  = (p < P_) ? rtf32(unw[gi]) : 0.f;
    g_fc2r[gi] = rtf32(fc2w[gi]);
    if (gi < NPAD_) g_unb[gi] = (gi < P_) ? unb[gi] : 0.f;
}

// ---------------- attention: gather qkv table, blended softmax over 2 keys ----------------
__global__ void attn_k(const int* __restrict__ x) {
    int warp = blockIdx.x * 8 + (threadIdx.x >> 5);
    int lane = threadIdx.x & 31;
    if (warp >= B_) return;
    int x0 = x[warp * 2 + 0];
    int x1 = x[warp * 2 + 1];
    const float* base0 = g_qkv + (size_t)x0 * (3 * D_);          // pos 0 row
    const float* base1 = g_qkv + (size_t)(P_ + x1) * (3 * D_);   // pos 1 row

    float s00[H_], s01[H_], s10[H_], s11[H_];
    #pragma unroll
    for (int h = 0; h < H_; h++) {
        int idx = h * DH_ + lane * 2;
        float2 q0 = *reinterpret_cast<const float2*>(base0 + idx);
        float2 k0 = *reinterpret_cast<const float2*>(base0 + 256 + idx);
        float2 q1 = *reinterpret_cast<const float2*>(base1 + idx);
        float2 k1 = *reinterpret_cast<const float2*>(base1 + 256 + idx);
        s00[h] = warpSum(q0.x * k0.x + q0.y * k0.y);
        s01[h] = warpSum(q0.x * k1.x + q0.y * k1.y);
        s10[h] = warpSum(q1.x * k0.x + q1.y * k0.y);
        s11[h] = warpSum(q1.x * k1.x + q1.y * k1.y);
    }

    float* z0row = g_z + (size_t)(warp * 2 + 0) * D_;
    float* z1row = g_z + (size_t)(warp * 2 + 1) * D_;
    const float scale = 0.125f;   // 1/sqrt(64)
    #pragma unroll
    for (int h = 0; h < H_; h++) {
        float a00 = s00[h] * scale, a01 = s01[h] * scale;
        float a10 = s10[h] * scale, a11 = s11[h] * scale;
        float m0 = fmaxf(a00, a01);
        float e00 = expf(a00 - m0), e01 = expf(a01 - m0);
        float r0 = 1.f / (e00 + e01);
        float p00 = 0.5f + 0.5f * e00 * r0;
        float p01 = 0.5f + 0.5f * e01 * r0;
        float m1 = fmaxf(a10, a11);
        float e10 = expf(a10 - m1), e11 = expf(a11 - m1);
        float r1 = 1.f / (e10 + e11);
        float p10 = 0.5f + 0.5f * e10 * r1;
        float p11 = 0.5f + 0.5f * e11 * r1;

        int idx = h * DH_ + lane * 2;
        float2 v0 = *reinterpret_cast<const float2*>(base0 + 512 + idx);
        float2 v1 = *reinterpret_cast<const float2*>(base1 + 512 + idx);
        float2 z0 = make_float2(rtf32(p00 * v0.x + p01 * v1.x), rtf32(p00 * v0.y + p01 * v1.y));
        float2 z1 = make_float2(rtf32(p10 * v0.x + p11 * v1.x), rtf32(p10 * v0.y + p11 * v1.y));
        *reinterpret_cast<float2*>(z0row + idx) = z0;
        *reinterpret_cast<float2*>(z1row + idx) = z1;
    }
}

// ---------------- tf32 GEMM: C[M x N] = A[M x K] * B[N x K]^T + bias ----------------
// STAGE 0: hid   = relu(z @ M1 + b1)        M=131072 K=256  N=1024
// STAGE 1: resid = hid @ fc2^T + fc2_b      M=131072 K=1024 N=256
// STAGE 2: out   = resid @ un_w^T + un_b    M=131072 K=256  N=1009 (padded 1024)
constexpr int BM = 128, BN = 128, BK = 32, LDT = BK + 4;   // +4 pad: conflict-free, 16B rows
constexpr int TILE_F = BM * LDT;                           // 4608 floats per tile buffer

// __launch_bounds__(256, 2): 2 CTAs/SM (regs capped 128, smem 2x73728 = 147KB fits).
// Second independent CTA hides per-tile __syncthreads + cp.async latency.
// NOTE (R7 fix): STAGE 2 stores MUST be scalar — NLD=1009 is odd, so
// row*NLD+col is only 4B-aligned for odd rows; float2 stores fault.
template<int STAGE>
__global__ __launch_bounds__(256, 2) void gemm_k(const float* __restrict__ extBias,
                                                 float* __restrict__ extOut) {
    constexpr int K   = (STAGE == 1) ? 1024 : 256;
    constexpr int KT  = K / BK;
    constexpr int NLD = (STAGE == 0) ? 1024 : (STAGE == 1) ? 256 : 1009;

    const float* Ag; const float* Bg; const float* bias; float* C;
    if      (STAGE == 0) { Ag = g_z;     Bg = g_M1T;  bias = g_b1;    C = g_hid;   }
    else if (STAGE == 1) { Ag = g_hid;   Bg = g_fc2r; bias = extBias; C = g_resid; }
    else                 { Ag = g_resid; Bg = g_unw;  bias = g_unb;   C = extOut;  }

    extern __shared__ float sm[];
    float* As = sm;                 // 2 buffers
    float* Bs = sm + 2 * TILE_F;    // 2 buffers

    int t     = threadIdx.x;
    int mbase = blockIdx.y * BM;
    int nbase = blockIdx.x * BN;

    auto load_tiles = [&](int buf, int k0) {
        #pragma unroll
        for (int i = 0; i < 4; i++) {
            int idx = t + i * 256;
            int row = idx >> 3;
            int c4  = (idx & 7) << 2;
            cpa16(As + buf * TILE_F + row * LDT + c4, Ag + (size_t)(mbase + row) * K + k0 + c4);
            cpa16(Bs + buf * TILE_F + row * LDT + c4, Bg + (size_t)(nbase + row) * K + k0 + c4);
        }
        cpa_commit();
    };

    load_tiles(0, 0);

    int wid = t >> 5, lane = t & 31;
    int wm = wid & 3, wn = wid >> 2;     // 4x2 warp grid: warp tile 32(M) x 64(N)
    int lq = lane >> 2, lr = lane & 3;

    float acc[2][8][4];
    #pragma unroll
    for (int i = 0; i < 2; i++)
        #pragma unroll
        for (int j = 0; j < 8; j++)
            #pragma unroll
            for (int r = 0; r < 4; r++) acc[i][j][r] = 0.f;

    for (int kt = 0; kt < KT; kt++) {
        if (kt + 1 < KT) { load_tiles((kt + 1) & 1, (kt + 1) * BK); cpa_wait<1>(); }
        else             { cpa_wait<0>(); }
        __syncthreads();
        const float* Ab = As + (kt & 1) * TILE_F;
        const float* Bb = Bs + (kt & 1) * TILE_F;
        #pragma unroll
        for (int ks = 0; ks < BK / 8; ks++) {
            int k0 = ks * 8 + lr;
            uint32_t afr[2][4];
            #pragma unroll
            for (int mt = 0; mt < 2; mt++) {
                int r0 = wm * 32 + mt * 16 + lq;
                afr[mt][0] = __float_as_uint(Ab[r0 * LDT + k0]);
                afr[mt][1] = __float_as_uint(Ab[(r0 + 8) * LDT + k0]);
                afr[mt][2] = __float_as_uint(Ab[r0 * LDT + k0 + 4]);
                afr[mt][3] = __float_as_uint(Ab[(r0 + 8) * LDT + k0 + 4]);
            }
            #pragma unroll
            for (int nt = 0; nt < 8; nt++) {
                int n0 = wn * 64 + nt * 8 + lq;
                uint32_t b0 = __float_as_uint(Bb[n0 * LDT + k0]);
                uint32_t b1 = __float_as_uint(Bb[n0 * LDT + k0 + 4]);
                mma8(acc[0][nt], afr[0], b0, b1);
                mma8(acc[1][nt], afr[1], b0, b1);
            }
        }
        __syncthreads();
    }

    // epilogue
    #pragma unroll
    for (int mt = 0; mt < 2; mt++) {
        int row = mbase + wm * 32 + mt * 16 + lq;
        #pragma unroll
        for (int nt = 0; nt < 8; nt++) {
            int col = nbase + wn * 64 + nt * 8 + lr * 2;
            float bb0 = bias[col], bb1 = bias[col + 1];
            float v00 = acc[mt][nt][0] + bb0;
            float v01 = acc[mt][nt][1] + bb1;
            float v10 = acc[mt][nt][2] + bb0;
            float v11 = acc[mt][nt][3] + bb1;
            if (STAGE == 0) {
                v00 = fmaxf(v00, 0.f); v01 = fmaxf(v01, 0.f);
                v10 = fmaxf(v10, 0.f); v11 = fmaxf(v11, 0.f);
            }
            if (STAGE != 2) {
                v00 = rtf32(v00); v01 = rtf32(v01);
                v10 = rtf32(v10); v11 = rtf32(v11);
            }
            if (STAGE == 2) {
                // scalar stores: NLD=1009 odd => float2 would be misaligned on odd rows
                size_t o0 = (size_t)row * NLD + col;
                size_t o1 = (size_t)(row + 8) * NLD + col;
                if (col < P_)     { C[o0]     = v00; C[o1]     = v10; }
                if (col + 1 < P_) { C[o0 + 1] = v01; C[o1 + 1] = v11; }
            } else {
                *reinterpret_cast<float2*>(C + (size_t)row * NLD + col)       = make_float2(v00, v01);
                *reinterpret_cast<float2*>(C + (size_t)(row + 8) * NLD + col) = make_float2(v10, v11);
            }
        }
    }
}

// ---------------- launcher ----------------
extern "C" void kernel_launch(void* const* d_in, const int* in_sizes, int n_in,
                              void* d_out, int out_size) {
    const int*   x    = (const int*)d_in[0];
    const float* tok  = (const float*)d_in[1];
    const float* pos  = (const float*)d_in[2];
    const float* WQ   = (const float*)d_in[3];
    const float* WK   = (const float*)d_in[4];
    const float* WV   = (const float*)d_in[5];
    const float* WO   = (const float*)d_in[6];
    const float* bQ   = (const float*)d_in[7];
    const float* bK   = (const float*)d_in[8];
    const float* bV   = (const float*)d_in[9];
    const float* bO   = (const float*)d_in[10];
    const float* fc1w = (const float*)d_in[11];
    const float* fc1b = (const float*)d_in[12];
    const float* fc2w = (const float*)d_in[13];
    const float* fc2b = (const float*)d_in[14];
    const float* unw  = (const float*)d_in[15];
    const float* unb  = (const float*)d_in[16];
    float* out = (float*)d_out;

    const int smem = 4 * TILE_F * (int)sizeof(float);   // 73728 B
    cudaFuncSetAttribute(gemm_k<0>, cudaFuncAttributeMaxDynamicSharedMemorySize, smem);
    cudaFuncSetAttribute(gemm_k<1>, cudaFuncAttributeMaxDynamicSharedMemorySize, smem);
    cudaFuncSetAttribute(gemm_k<2>, cudaFuncAttributeMaxDynamicSharedMemorySize, smem);

    pk_qkv <<<253,  256>>>(tok, pos, WQ, WK, WV, bQ, bK, bV);
    pk_m1  <<<256,  256>>>(WO, fc1w);
    pk_b1  <<<4,    256>>>(bO, fc1w, fc1b);
    pk_copy<<<1024, 256>>>(unw, unb, fc2w);
    attn_k <<<8192, 256>>>(x);

    gemm_k<0><<<dim3(8, 1024), 256, smem>>>(nullptr, nullptr);   // z -> hid
    gemm_k<1><<<dim3(2, 1024), 256, smem>>>(fc2b,    nullptr);   // hid -> resid
    gemm_k<2><<<dim3(8, 1024), 256, smem>>>(nullptr, out);       // resid -> logits
}

// round 9
// speedup vs baseline: 1.8400x; 1.8094x over previous
#include <cuda_runtime.h>
#include <cuda_bf16.h>
#include <cstdint>
#include <math.h>

#define DEV_INLINE __device__ __forceinline__

// ---------------- problem constants ----------------
constexpr int B_    = 65536;
constexpr int SEQ_  = 2;
constexpr int P_    = 1009;
constexpr int D_    = 256;
constexpr int H_    = 4;
constexpr int DH_   = 64;
constexpr int HID_  = 1024;
constexpr int M_    = B_ * SEQ_;   // 131072 rows
constexpr int NPAD_ = 1024;        // padded unembed N

// ---------------- scratch (static device globals; allocation-free rule) ----------------
__device__ __align__(16) float          g_qkv [SEQ_ * P_ * 3 * D_];   // fp32 QKV table
__device__ __align__(16) __nv_bfloat16  g_M1T [HID_ * D_];            // (W_O @ fc1^T)^T bf16
__device__ __align__(16) float          g_b1  [HID_];
__device__ __align__(16) __nv_bfloat16  g_fc2b[D_ * HID_];            // fc2_w bf16
__device__ __align__(16) __nv_bfloat16  g_unw [NPAD_ * D_];           // un_w bf16 zero-padded
__device__ __align__(16) float          g_unb [NPAD_];
__device__ __align__(16) __nv_bfloat16  g_z    [(size_t)M_ * D_];     // attention out bf16
__device__ __align__(16) __nv_bfloat16  g_hid  [(size_t)M_ * HID_];   // relu hidden bf16
__device__ __align__(16) __nv_bfloat16  g_resid[(size_t)M_ * D_];     // fc2 out bf16

// ---------------- helpers ----------------
DEV_INLINE float warpSum(float v) {
    #pragma unroll
    for (int off = 16; off; off >>= 1) v += __shfl_xor_sync(0xffffffffu, v, off);
    return v;
}

// pack two fp32 -> bf16x2 (lo = first arg, hi = second arg)
DEV_INLINE uint32_t packbf(float lo, float hi) {
    uint32_t r;
    asm volatile("cvt.rn.bf16x2.f32 %0, %1, %2;" : "=r"(r) : "f"(hi), "f"(lo));
    return r;
}

DEV_INLINE void cpa16(uint32_t dst_s, const void* src) {
    asm volatile("cp.async.cg.shared.global [%0], [%1], 16;" :: "r"(dst_s), "l"(src));
}
DEV_INLINE void cpa_commit() { asm volatile("cp.async.commit_group;"); }
template<int N> DEV_INLINE void cpa_wait() { asm volatile("cp.async.wait_group %0;" :: "n"(N)); }

DEV_INLINE void ldsm4(uint32_t* r, uint32_t addr) {
    asm volatile("ldmatrix.sync.aligned.m8n8.x4.shared.b16 {%0,%1,%2,%3}, [%4];"
                 : "=r"(r[0]), "=r"(r[1]), "=r"(r[2]), "=r"(r[3]) : "r"(addr));
}

// m16n8k16 bf16 mma, fp32 accumulate
DEV_INLINE void mma16(float* c, const uint32_t* a, uint32_t b0, uint32_t b1) {
    asm volatile(
        "mma.sync.aligned.m16n8k16.row.col.f32.bf16.bf16.f32 "
        "{%0,%1,%2,%3},{%4,%5,%6,%7},{%8,%9},{%0,%1,%2,%3};"
        : "+f"(c[0]), "+f"(c[1]), "+f"(c[2]), "+f"(c[3])
        : "r"(a[0]), "r"(a[1]), "r"(a[2]), "r"(a[3]), "r"(b0), "r"(b1));
}

DEV_INLINE uint32_t swz(uint32_t o) { return o ^ ((o >> 3) & 0x70u); }

// ---------------- PK1: QKV table for all 2018 (pos, token) rows (fp32) ----------------
__global__ void pk_qkv(const float* __restrict__ tok, const float* __restrict__ pos,
                       const float* __restrict__ WQ, const float* __restrict__ WK,
                       const float* __restrict__ WV, const float* __restrict__ bQ,
                       const float* __restrict__ bK, const float* __restrict__ bV) {
    __shared__ float hv[8][D_];
    int t   = threadIdx.x;                  // 0..255 == he
    int sp0 = blockIdx.x * 8;
    #pragma unroll
    for (int r = 0; r < 8; r++) {
        int sp = sp0 + r;
        if (sp < SEQ_ * P_) {
            int s = sp / P_, p = sp % P_;
            hv[r][t] = tok[p * D_ + t] + pos[s * D_ + t];
        } else hv[r][t] = 0.f;
    }
    __syncthreads();
    int h = t >> 6, e = t & 63;
    const float* wq = WQ + h * D_ * DH_ + e;
    const float* wk = WK + h * D_ * DH_ + e;
    const float* wv = WV + h * D_ * DH_ + e;
    float aq[8] = {}, ak[8] = {}, av[8] = {};
    for (int d = 0; d < D_; d++) {
        float q = wq[d * DH_], k = wk[d * DH_], v = wv[d * DH_];
        #pragma unroll
        for (int r = 0; r < 8; r++) {
            float hd = hv[r][d];
            aq[r] += q * hd; ak[r] += k * hd; av[r] += v * hd;
        }
    }
    float bq = bQ[t], bk = bK[t], bv = bV[t];
    #pragma unroll
    for (int r = 0; r < 8; r++) {
        int sp = sp0 + r;
        if (sp < SEQ_ * P_) {
            float* o = g_qkv + (size_t)sp * (3 * D_);
            o[t] = aq[r] + bq; o[256 + t] = ak[r] + bk; o[512 + t] = av[r] + bv;
        }
    }
}

// ---------------- PK2: M1T[j][he] = sum_d W_O[he][d] * fc1_w[j][d]  -> bf16 ----------
__global__ void pk_m1(const float* __restrict__ WO, const float* __restrict__ fc1w) {
    __shared__ float sf[4][D_];
    int t  = threadIdx.x;
    int j0 = blockIdx.x * 4;
    #pragma unroll
    for (int r = 0; r < 4; r++) sf[r][t] = fc1w[(j0 + r) * D_ + t];
    __syncthreads();
    const float* w = WO + t * D_;
    float acc[4] = {};
    for (int d = 0; d < D_; d++) {
        float wd = w[d];
        #pragma unroll
        for (int r = 0; r < 4; r++) acc[r] += wd * sf[r][d];
    }
    #pragma unroll
    for (int r = 0; r < 4; r++) g_M1T[(j0 + r) * D_ + t] = __float2bfloat16_rn(acc[r]);
}

// ---------------- PKb: b1 = b_O @ fc1^T + fc1_b (fp32) ----------------
__global__ void pk_b1(const float* __restrict__ bO, const float* __restrict__ fc1w,
                      const float* __restrict__ fc1b) {
    int j = blockIdx.x * blockDim.x + threadIdx.x;   // 0..1023
    float acc = fc1b[j];
    for (int d = 0; d < D_; d++) acc += bO[d] * fc1w[j * D_ + d];
    g_b1[j] = acc;
}

// ---------------- PKc: bf16 copies of un_w (padded), fc2_w; padded un_b ----------------
__global__ void pk_copy(const float* __restrict__ unw, const float* __restrict__ unb,
                        const float* __restrict__ fc2w) {
    int gi = blockIdx.x * blockDim.x + threadIdx.x;  // 0..262143
    int p  = gi >> 8;
    g_unw[gi]  = __float2bfloat16_rn((p < P_) ? unw[gi] : 0.f);
    g_fc2b[gi] = __float2bfloat16_rn(fc2w[gi]);
    if (gi < NPAD_) g_unb[gi] = (gi < P_) ? unb[gi] : 0.f;
}

// ---------------- attention: gather qkv table, blended softmax, z -> bf16 ------------
__global__ void attn_k(const int* __restrict__ x) {
    int warp = blockIdx.x * 8 + (threadIdx.x >> 5);
    int lane = threadIdx.x & 31;
    if (warp >= B_) return;
    int x0 = x[warp * 2 + 0];
    int x1 = x[warp * 2 + 1];
    const float* base0 = g_qkv + (size_t)x0 * (3 * D_);          // pos 0 row
    const float* base1 = g_qkv + (size_t)(P_ + x1) * (3 * D_);   // pos 1 row

    float s00[H_], s01[H_], s10[H_], s11[H_];
    #pragma unroll
    for (int h = 0; h < H_; h++) {
        int idx = h * DH_ + lane * 2;
        float2 q0 = *reinterpret_cast<const float2*>(base0 + idx);
        float2 k0 = *reinterpret_cast<const float2*>(base0 + 256 + idx);
        float2 q1 = *reinterpret_cast<const float2*>(base1 + idx);
        float2 k1 = *reinterpret_cast<const float2*>(base1 + 256 + idx);
        s00[h] = warpSum(q0.x * k0.x + q0.y * k0.y);
        s01[h] = warpSum(q0.x * k1.x + q0.y * k1.y);
        s10[h] = warpSum(q1.x * k0.x + q1.y * k0.y);
        s11[h] = warpSum(q1.x * k1.x + q1.y * k1.y);
    }

    uint32_t* z0row = reinterpret_cast<uint32_t*>(g_z + (size_t)(warp * 2 + 0) * D_);
    uint32_t* z1row = reinterpret_cast<uint32_t*>(g_z + (size_t)(warp * 2 + 1) * D_);
    const float scale = 0.125f;   // 1/sqrt(64)
    #pragma unroll
    for (int h = 0; h < H_; h++) {
        float a00 = s00[h] * scale, a01 = s01[h] * scale;
        float a10 = s10[h] * scale, a11 = s11[h] * scale;
        float m0 = fmaxf(a00, a01);
        float e00 = expf(a00 - m0), e01 = expf(a01 - m0);
        float r0 = 1.f / (e00 + e01);
        float p00 = 0.5f + 0.5f * e00 * r0;
        float p01 = 0.5f + 0.5f * e01 * r0;
        float m1 = fmaxf(a10, a11);
        float e10 = expf(a10 - m1), e11 = expf(a11 - m1);
        float r1 = 1.f / (e10 + e11);
        float p10 = 0.5f + 0.5f * e10 * r1;
        float p11 = 0.5f + 0.5f * e11 * r1;

        int idx = h * DH_ + lane * 2;
        float2 v0 = *reinterpret_cast<const float2*>(base0 + 512 + idx);
        float2 v1 = *reinterpret_cast<const float2*>(base1 + 512 + idx);
        z0row[idx >> 1] = packbf(p00 * v0.x + p01 * v1.x, p00 * v0.y + p01 * v1.y);
        z1row[idx >> 1] = packbf(p10 * v0.x + p11 * v1.x, p10 * v0.y + p11 * v1.y);
    }
}

// ---------------- bf16 GEMM: C[M x N] = A[M x K] * B[N x K]^T + bias ----------------
// STAGE 0: hid   = relu(z @ M1 + b1)        M=131072 K=256  N=1024  (bf16 out)
// STAGE 1: resid = hid @ fc2^T + fc2_b      M=131072 K=1024 N=256   (bf16 out)
// STAGE 2: out   = resid @ un_w^T + un_b    M=131072 K=256  N=1009  (fp32 out, scalar stores)
//
// BM=BN=128, BK=64 bf16 (128B rows, xor-swizzled). ldmatrix.x4 fragment loads.
// smem: 2 x (A 16KB + B 16KB) = 64KB -> 2 CTAs/SM.
constexpr int BM = 128, BN = 128, BK = 64;
constexpr int TILE_B = BM * BK * 2;        // 16384 bytes
constexpr int SMEM_T = 4 * TILE_B;         // 65536

template<int STAGE>
__global__ __launch_bounds__(256, 2) void gemm_b(const float* __restrict__ extBias,
                                                 float* __restrict__ extOut) {
    constexpr int K   = (STAGE == 1) ? 1024 : 256;
    constexpr int KT  = K / BK;
    constexpr int NLD = (STAGE == 0) ? 1024 : (STAGE == 1) ? 256 : 1009;

    const __nv_bfloat16* Ag; const __nv_bfloat16* Bg; const float* bias;
    __nv_bfloat16* Cb = nullptr; float* Cf = nullptr;
    if      (STAGE == 0) { Ag = g_z;     Bg = g_M1T;  bias = g_b1;    Cb = g_hid;   }
    else if (STAGE == 1) { Ag = g_hid;   Bg = g_fc2b; bias = extBias; Cb = g_resid; }
    else                 { Ag = g_resid; Bg = g_unw;  bias = g_unb;   Cf = extOut;  }

    extern __shared__ char sm[];
    const uint32_t smb = (uint32_t)__cvta_generic_to_shared(sm);

    int t     = threadIdx.x;
    int mbase = blockIdx.y * BM;
    int nbase = blockIdx.x * BN;

    // A buffers at smb + buf*TILE_B ; B buffers at smb + 2*TILE_B + buf*TILE_B
    auto load_tiles = [&](int buf, int kt) {
        #pragma unroll
        for (int i = 0; i < 4; i++) {
            int idx = i * 256 + t;            // 0..1023 16B chunks per matrix
            int row = idx >> 3;
            int c16 = idx & 7;
            uint32_t off = swz((uint32_t)(row * 128 + c16 * 16));
            cpa16(smb + buf * TILE_B + off,
                  Ag + (size_t)(mbase + row) * K + kt * BK + c16 * 8);
            cpa16(smb + 2 * TILE_B + buf * TILE_B + off,
                  Bg + (size_t)(nbase + row) * K + kt * BK + c16 * 8);
        }
        cpa_commit();
    };

    load_tiles(0, 0);

    int wid = t >> 5, L = t & 31;
    int wm = wid & 3, wn = wid >> 2;     // 4x2 warp grid: warp tile 32(M) x 64(N)
    int lq = L >> 2, lr = L & 3;

    // ldmatrix lane-derived offsets
    int a_row = (((L >> 3) & 1) << 3) + (L & 7);   // row within 16-row A fragment
    int a_kb  = (L >> 4) << 4;                      // k-byte half (0/16)
    int b_row = ((L >> 4) << 3) + (L & 7);          // row within 16-row B pair
    int b_kb  = ((L >> 3) & 1) << 4;

    float acc[2][8][4];
    #pragma unroll
    for (int i = 0; i < 2; i++)
        #pragma unroll
        for (int j = 0; j < 8; j++)
            #pragma unroll
            for (int r = 0; r < 4; r++) acc[i][j][r] = 0.f;

    for (int kt = 0; kt < KT; kt++) {
        if (kt + 1 < KT) { load_tiles((kt + 1) & 1, kt + 1); cpa_wait<1>(); }
        else             { cpa_wait<0>(); }
        __syncthreads();
        uint32_t Abase = smb + (kt & 1) * TILE_B;
        uint32_t Bbase = smb + 2 * TILE_B + ((kt & 1)) * TILE_B;
        #pragma unroll
        for (int ks = 0; ks < BK / 16; ks++) {
            uint32_t A0[4], A1[4];
            ldsm4(A0, Abase + swz((uint32_t)((wm * 32 + a_row) * 128 + ks * 32 + a_kb)));
            ldsm4(A1, Abase + swz((uint32_t)((wm * 32 + 16 + a_row) * 128 + ks * 32 + a_kb)));
            #pragma unroll
            for (int p = 0; p < 4; p++) {
                uint32_t Bf[4];
                ldsm4(Bf, Bbase + swz((uint32_t)((wn * 64 + p * 16 + b_row) * 128 + ks * 32 + b_kb)));
                mma16(acc[0][2 * p],     A0, Bf[0], Bf[1]);
                mma16(acc[1][2 * p],     A1, Bf[0], Bf[1]);
                mma16(acc[0][2 * p + 1], A0, Bf[2], Bf[3]);
                mma16(acc[1][2 * p + 1], A1, Bf[2], Bf[3]);
            }
        }
        __syncthreads();
    }

    // epilogue: acc[mt][nt] = {(r,c),(r,c+1),(r+8,c),(r+8,c+1)}
    #pragma unroll
    for (int mt = 0; mt < 2; mt++) {
        int row = mbase + wm * 32 + mt * 16 + lq;
        #pragma unroll
        for (int nt = 0; nt < 8; nt++) {
            int col = nbase + wn * 64 + nt * 8 + lr * 2;
            float bb0 = bias[col], bb1 = bias[col + 1];
            float v00 = acc[mt][nt][0] + bb0;
            float v01 = acc[mt][nt][1] + bb1;
            float v10 = acc[mt][nt][2] + bb0;
            float v11 = acc[mt][nt][3] + bb1;
            if (STAGE == 0) {
                v00 = fmaxf(v00, 0.f); v01 = fmaxf(v01, 0.f);
                v10 = fmaxf(v10, 0.f); v11 = fmaxf(v11, 0.f);
            }
            if (STAGE == 2) {
                // scalar fp32 stores: NLD=1009 odd (alignment), plus P_ guard
                size_t o0 = (size_t)row * NLD + col;
                size_t o1 = (size_t)(row + 8) * NLD + col;
                if (col < P_)     { Cf[o0]     = v00; Cf[o1]     = v10; }
                if (col + 1 < P_) { Cf[o0 + 1] = v01; Cf[o1 + 1] = v11; }
            } else {
                *reinterpret_cast<uint32_t*>(Cb + (size_t)row * NLD + col)       = packbf(v00, v01);
                *reinterpret_cast<uint32_t*>(Cb + (size_t)(row + 8) * NLD + col) = packbf(v10, v11);
            }
        }
    }
}

// ---------------- launcher ----------------
extern "C" void kernel_launch(void* const* d_in, const int* in_sizes, int n_in,
                              void* d_out, int out_size) {
    const int*   x    = (const int*)d_in[0];
    const float* tok  = (const float*)d_in[1];
    const float* pos  = (const float*)d_in[2];
    const float* WQ   = (const float*)d_in[3];
    const float* WK   = (const float*)d_in[4];
    const float* WV   = (const float*)d_in[5];
    const float* WO   = (const float*)d_in[6];
    const float* bQ   = (const float*)d_in[7];
    const float* bK   = (const float*)d_in[8];
    const float* bV   = (const float*)d_in[9];
    const float* bO   = (const float*)d_in[10];
    const float* fc1w = (const float*)d_in[11];
    const float* fc1b = (const float*)d_in[12];
    const float* fc2w = (const float*)d_in[13];
    const float* fc2b = (const float*)d_in[14];
    const float* unw  = (const float*)d_in[15];
    const float* unb  = (const float*)d_in[16];
    float* out = (float*)d_out;

    cudaFuncSetAttribute(gemm_b<0>, cudaFuncAttributeMaxDynamicSharedMemorySize, SMEM_T);
    cudaFuncSetAttribute(gemm_b<1>, cudaFuncAttributeMaxDynamicSharedMemorySize, SMEM_T);
    cudaFuncSetAttribute(gemm_b<2>, cudaFuncAttributeMaxDynamicSharedMemorySize, SMEM_T);

    pk_qkv <<<253,  256>>>(tok, pos, WQ, WK, WV, bQ, bK, bV);
    pk_m1  <<<256,  256>>>(WO, fc1w);
    pk_b1  <<<4,    256>>>(bO, fc1w, fc1b);
    pk_copy<<<1024, 256>>>(unw, unb, fc2w);
    attn_k <<<8192, 256>>>(x);

    gemm_b<0><<<dim3(8, 1024), 256, SMEM_T>>>(nullptr, nullptr);   // z -> hid
    gemm_b<1><<<dim3(2, 1024), 256, SMEM_T>>>(fc2b,    nullptr);   // hid -> resid
    gemm_b<2><<<dim3(8, 1024), 256, SMEM_T>>>(nullptr, out);       // resid -> logits
}

// round 12
// speedup vs baseline: 1.8413x; 1.0007x over previous
#include <cuda_runtime.h>
#include <cuda_fp16.h>
#include <cstdint>
#include <math.h>

#define DEV_INLINE __device__ __forceinline__

// ---------------- problem constants ----------------
constexpr int B_    = 65536;
constexpr int SEQ_  = 2;
constexpr int P_    = 1009;
constexpr int D_    = 256;
constexpr int H_    = 4;
constexpr int DH_   = 64;
constexpr int HID_  = 1024;
constexpr int M_    = B_ * SEQ_;   // 131072 rows
constexpr int NPAD_ = 1024;        // padded unembed N

// ---------------- scratch (static device globals; allocation-free rule) ----------------
__device__ __align__(16) float  g_qkv [SEQ_ * P_ * 3 * D_];   // fp32 QKV table
__device__ __align__(16) __half g_M1T [HID_ * D_];            // (W_O @ fc1^T)^T fp16
__device__ __align__(16) float  g_b1  [HID_];
__device__ __align__(16) __half g_fc2h[D_ * HID_];            // fc2_w fp16
__device__ __align__(16) __half g_unw [NPAD_ * D_];           // un_w fp16 zero-padded
__device__ __align__(16) float  g_unb [NPAD_];
__device__ __align__(16) __half g_z    [(size_t)M_ * D_];     // attention out fp16
__device__ __align__(16) __half g_hid  [(size_t)M_ * HID_];   // relu hidden fp16
__device__ __align__(16) __half g_resid[(size_t)M_ * D_];     // fc2 out fp16

// ---------------- helpers ----------------
DEV_INLINE float warpSum(float v) {
    #pragma unroll
    for (int off = 16; off; off >>= 1) v += __shfl_xor_sync(0xffffffffu, v, off);
    return v;
}

// pack two fp32 -> f16x2 (lo = first arg in low half)
DEV_INLINE uint32_t packh(float lo, float hi) {
    uint32_t r;
    asm volatile("cvt.rn.f16x2.f32 %0, %1, %2;" : "=r"(r) : "f"(hi), "f"(lo));
    return r;
}

DEV_INLINE void cpa16(uint32_t dst_s, const void* src) {
    asm volatile("cp.async.cg.shared.global [%0], [%1], 16;" :: "r"(dst_s), "l"(src));
}
DEV_INLINE void cpa_commit() { asm volatile("cp.async.commit_group;"); }
template<int N> DEV_INLINE void cpa_wait() { asm volatile("cp.async.wait_group %0;" :: "n"(N)); }

DEV_INLINE void ldsm4(uint32_t* r, uint32_t addr) {
    asm volatile("ldmatrix.sync.aligned.m8n8.x4.shared.b16 {%0,%1,%2,%3}, [%4];"
                 : "=r"(r[0]), "=r"(r[1]), "=r"(r[2]), "=r"(r[3]) : "r"(addr));
}

// m16n8k16 fp16 mma, fp32 accumulate
DEV_INLINE void mma16(float* c, const uint32_t* a, uint32_t b0, uint32_t b1) {
    asm volatile(
        "mma.sync.aligned.m16n8k16.row.col.f32.f16.f16.f32 "
        "{%0,%1,%2,%3},{%4,%5,%6,%7},{%8,%9},{%0,%1,%2,%3};"
        : "+f"(c[0]), "+f"(c[1]), "+f"(c[2]), "+f"(c[3])
        : "r"(a[0]), "r"(a[1]), "r"(a[2]), "r"(a[3]), "r"(b0), "r"(b1));
}

DEV_INLINE uint32_t swz(uint32_t o) { return o ^ ((o >> 3) & 0x70u); }

// ---------------- PK1: QKV table for all 2018 (pos, token) rows (fp32) ----------------
__global__ void pk_qkv(const float* __restrict__ tok, const float* __restrict__ pos,
                       const float* __restrict__ WQ, const float* __restrict__ WK,
                       const float* __restrict__ WV, const float* __restrict__ bQ,
                       const float* __restrict__ bK, const float* __restrict__ bV) {
    __shared__ float hv[8][D_];
    int t   = threadIdx.x;                  // 0..255 == he
    int sp0 = blockIdx.x * 8;
    #pragma unroll
    for (int r = 0; r < 8; r++) {
        int sp = sp0 + r;
        if (sp < SEQ_ * P_) {
            int s = sp / P_, p = sp % P_;
            hv[r][t] = tok[p * D_ + t] + pos[s * D_ + t];
        } else hv[r][t] = 0.f;
    }
    __syncthreads();
    int h = t >> 6, e = t & 63;
    const float* wq = WQ + h * D_ * DH_ + e;
    const float* wk = WK + h * D_ * DH_ + e;
    const float* wv = WV + h * D_ * DH_ + e;
    float aq[8] = {}, ak[8] = {}, av[8] = {};
    for (int d = 0; d < D_; d++) {
        float q = wq[d * DH_], k = wk[d * DH_], v = wv[d * DH_];
        #pragma unroll
        for (int r = 0; r < 8; r++) {
            float hd = hv[r][d];
            aq[r] += q * hd; ak[r] += k * hd; av[r] += v * hd;
        }
    }
    float bq = bQ[t], bk = bK[t], bv = bV[t];
    #pragma unroll
    for (int r = 0; r < 8; r++) {
        int sp = sp0 + r;
        if (sp < SEQ_ * P_) {
            float* o = g_qkv + (size_t)sp * (3 * D_);
            o[t] = aq[r] + bq; o[256 + t] = ak[r] + bk; o[512 + t] = av[r] + bv;
        }
    }
}

// ---------------- PK2: M1T[j][he] = sum_d W_O[he][d] * fc1_w[j][d]  -> fp16 ----------
__global__ void pk_m1(const float* __restrict__ WO, const float* __restrict__ fc1w) {
    __shared__ float sf[4][D_];
    int t  = threadIdx.x;
    int j0 = blockIdx.x * 4;
    #pragma unroll
    for (int r = 0; r < 4; r++) sf[r][t] = fc1w[(j0 + r) * D_ + t];
    __syncthreads();
    const float* w = WO + t * D_;
    float acc[4] = {};
    for (int d = 0; d < D_; d++) {
        float wd = w[d];
        #pragma unroll
        for (int r = 0; r < 4; r++) acc[r] += wd * sf[r][d];
    }
    #pragma unroll
    for (int r = 0; r < 4; r++) g_M1T[(j0 + r) * D_ + t] = __float2half_rn(acc[r]);
}

// ---------------- PKb: b1 = b_O @ fc1^T + fc1_b (fp32) ----------------
__global__ void pk_b1(const float* __restrict__ bO, const float* __restrict__ fc1w,
                      const float* __restrict__ fc1b) {
    int j = blockIdx.x * blockDim.x + threadIdx.x;   // 0..1023
    float acc = fc1b[j];
    for (int d = 0; d < D_; d++) acc += bO[d] * fc1w[j * D_ + d];
    g_b1[j] = acc;
}

// ---------------- PKc: fp16 copies of un_w (padded), fc2_w; padded un_b ----------------
__global__ void pk_copy(const float* __restrict__ unw, const float* __restrict__ unb,
                        const float* __restrict__ fc2w) {
    int gi = blockIdx.x * blockDim.x + threadIdx.x;  // 0..262143
    int p  = gi >> 8;
    g_unw[gi]  = __float2half_rn((p < P_) ? unw[gi] : 0.f);
    g_fc2h[gi] = __float2half_rn(fc2w[gi]);
    if (gi < NPAD_) g_unb[gi] = (gi < P_) ? unb[gi] : 0.f;
}

// ---------------- attention: gather qkv table, blended softmax, z -> fp16 ------------
__global__ void attn_k(const int* __restrict__ x) {
    int warp = blockIdx.x * 8 + (threadIdx.x >> 5);
    int lane = threadIdx.x & 31;
    if (warp >= B_) return;
    int x0 = x[warp * 2 + 0];
    int x1 = x[warp * 2 + 1];
    const float* base0 = g_qkv + (size_t)x0 * (3 * D_);          // pos 0 row
    const float* base1 = g_qkv + (size_t)(P_ + x1) * (3 * D_);   // pos 1 row

    float s00[H_], s01[H_], s10[H_], s11[H_];
    #pragma unroll
    for (int h = 0; h < H_; h++) {
        int idx = h * DH_ + lane * 2;
        float2 q0 = *reinterpret_cast<const float2*>(base0 + idx);
        float2 k0 = *reinterpret_cast<const float2*>(base0 + 256 + idx);
        float2 q1 = *reinterpret_cast<const float2*>(base1 + idx);
        float2 k1 = *reinterpret_cast<const float2*>(base1 + 256 + idx);
        s00[h] = warpSum(q0.x * k0.x + q0.y * k0.y);
        s01[h] = warpSum(q0.x * k1.x + q0.y * k1.y);
        s10[h] = warpSum(q1.x * k0.x + q1.y * k0.y);
        s11[h] = warpSum(q1.x * k1.x + q1.y * k1.y);
    }

    uint32_t* z0row = reinterpret_cast<uint32_t*>(g_z + (size_t)(warp * 2 + 0) * D_);
    uint32_t* z1row = reinterpret_cast<uint32_t*>(g_z + (size_t)(warp * 2 + 1) * D_);
    const float scale = 0.125f;   // 1/sqrt(64)
    #pragma unroll
    for (int h = 0; h < H_; h++) {
        float a00 = s00[h] * scale, a01 = s01[h] * scale;
        float a10 = s10[h] * scale, a11 = s11[h] * scale;
        float m0 = fmaxf(a00, a01);
        float e00 = expf(a00 - m0), e01 = expf(a01 - m0);
        float r0 = 1.f / (e00 + e01);
        float p00 = 0.5f + 0.5f * e00 * r0;
        float p01 = 0.5f + 0.5f * e01 * r0;
        float m1 = fmaxf(a10, a11);
        float e10 = expf(a10 - m1), e11 = expf(a11 - m1);
        float r1 = 1.f / (e10 + e11);
        float p10 = 0.5f + 0.5f * e10 * r1;
        float p11 = 0.5f + 0.5f * e11 * r1;

        int idx = h * DH_ + lane * 2;
        float2 v0 = *reinterpret_cast<const float2*>(base0 + 512 + idx);
        float2 v1 = *reinterpret_cast<const float2*>(base1 + 512 + idx);
        z0row[idx >> 1] = packh(p00 * v0.x + p01 * v1.x, p00 * v0.y + p01 * v1.y);
        z1row[idx >> 1] = packh(p10 * v0.x + p11 * v1.x, p10 * v0.y + p11 * v1.y);
    }
}

// ---------------- fp16 GEMM: C[M x N] = A[M x K] * B[N x K]^T + bias ----------------
// STAGE 0: hid   = relu(z @ M1 + b1)        M=131072 K=256  N=1024  (fp16 out)
// STAGE 1: resid = hid @ fc2^T + fc2_b      M=131072 K=1024 N=256   (fp16 out)
// STAGE 2: out   = resid @ un_w^T + un_b    M=131072 K=256  N=1009  (fp32 out, scalar stores)
//
// BM=BN=128, BK=64 fp16 (128B rows, xor-swizzled). ldmatrix.x4 fragment loads.
// Single __syncthreads per K-tile: with double buffering, issuing the next
// cp.async AFTER the barrier is race-free (prior-iter MMAs on the target
// buffer completed before each warp reached the barrier).
constexpr int BM = 128, BN = 128, BK = 64;
constexpr int TILE_B = BM * BK * 2;        // 16384 bytes
constexpr int SMEM_T = 4 * TILE_B;         // 65536

template<int STAGE>
__global__ __launch_bounds__(256, 2) void gemm_h(const float* __restrict__ extBias,
                                                 float* __restrict__ extOut) {
    constexpr int K   = (STAGE == 1) ? 1024 : 256;
    constexpr int KT  = K / BK;
    constexpr int NLD = (STAGE == 0) ? 1024 : (STAGE == 1) ? 256 : 1009;

    const __half* Ag; const __half* Bg; const float* bias;
    __half* Ch = nullptr; float* Cf = nullptr;
    if      (STAGE == 0) { Ag = g_z;     Bg = g_M1T;  bias = g_b1;    Ch = g_hid;   }
    else if (STAGE == 1) { Ag = g_hid;   Bg = g_fc2h; bias = extBias; Ch = g_resid; }
    else                 { Ag = g_resid; Bg = g_unw;  bias = g_unb;   Cf = extOut;  }

    extern __shared__ char sm[];
    const uint32_t smb = (uint32_t)__cvta_generic_to_shared(sm);

    int t     = threadIdx.x;
    int mbase = blockIdx.y * BM;
    int nbase = blockIdx.x * BN;

    // A buffers at smb + buf*TILE_B ; B buffers at smb + 2*TILE_B + buf*TILE_B
    auto load_tiles = [&](int buf, int kt) {
        #pragma unroll
        for (int i = 0; i < 4; i++) {
            int idx = i * 256 + t;            // 0..1023 16B chunks per matrix
            int row = idx >> 3;
            int c16 = idx & 7;
            uint32_t off = swz((uint32_t)(row * 128 + c16 * 16));
            cpa16(smb + buf * TILE_B + off,
                  Ag + (size_t)(mbase + row) * K + kt * BK + c16 * 8);
            cpa16(smb + 2 * TILE_B + buf * TILE_B + off,
                  Bg + (size_t)(nbase + row) * K + kt * BK + c16 * 8);
        }
        cpa_commit();
    };

    load_tiles(0, 0);

    int wid = t >> 5, L = t & 31;
    int wm = wid & 3, wn = wid >> 2;     // 4x2 warp grid: warp tile 32(M) x 64(N)
    int lq = L >> 2, lr = L & 3;

    // ldmatrix lane-derived offsets
    int a_row = (((L >> 3) & 1) << 3) + (L & 7);   // row within 16-row A fragment
    int a_kb  = (L >> 4) << 4;                      // k-byte half (0/16)
    int b_row = ((L >> 4) << 3) + (L & 7);          // row within 16-row B pair
    int b_kb  = ((L >> 3) & 1) << 4;

    float acc[2][8][4];
    #pragma unroll
    for (int i = 0; i < 2; i++)
        #pragma unroll
        for (int j = 0; j < 8; j++)
            #pragma unroll
            for (int r = 0; r < 4; r++) acc[i][j][r] = 0.f;

    for (int kt = 0; kt < KT; kt++) {
        cpa_wait<0>();
        __syncthreads();
        if (kt + 1 < KT) load_tiles((kt + 1) & 1, kt + 1);   // overlaps with MMAs below
        uint32_t Abase = smb + (kt & 1) * TILE_B;
        uint32_t Bbase = smb + 2 * TILE_B + (kt & 1) * TILE_B;
        #pragma unroll
        for (int ks = 0; ks < BK / 16; ks++) {
            uint32_t A0[4], A1[4];
            ldsm4(A0, Abase + swz((uint32_t)((wm * 32 + a_row) * 128 + ks * 32 + a_kb)));
            ldsm4(A1, Abase + swz((uint32_t)((wm * 32 + 16 + a_row) * 128 + ks * 32 + a_kb)));
            #pragma unroll
            for (int p = 0; p < 4; p++) {
                uint32_t Bf[4];
                ldsm4(Bf, Bbase + swz((uint32_t)((wn * 64 + p * 16 + b_row) * 128 + ks * 32 + b_kb)));
                mma16(acc[0][2 * p],     A0, Bf[0], Bf[1]);
                mma16(acc[1][2 * p],     A1, Bf[0], Bf[1]);
                mma16(acc[0][2 * p + 1], A0, Bf[2], Bf[3]);
                mma16(acc[1][2 * p + 1], A1, Bf[2], Bf[3]);
            }
        }
    }

    // epilogue: acc[mt][nt] = {(r,c),(r,c+1),(r+8,c),(r+8,c+1)}
    #pragma unroll
    for (int mt = 0; mt < 2; mt++) {
        int row = mbase + wm * 32 + mt * 16 + lq;
        #pragma unroll
        for (int nt = 0; nt < 8; nt++) {
            int col = nbase + wn * 64 + nt * 8 + lr * 2;
            float bb0 = bias[col], bb1 = bias[col + 1];
            float v00 = acc[mt][nt][0] + bb0;
            float v01 = acc[mt][nt][1] + bb1;
            float v10 = acc[mt][nt][2] + bb0;
            float v11 = acc[mt][nt][3] + bb1;
            if (STAGE == 0) {
                v00 = fmaxf(v00, 0.f); v01 = fmaxf(v01, 0.f);
                v10 = fmaxf(v10, 0.f); v11 = fmaxf(v11, 0.f);
            }
            if (STAGE == 2) {
                // scalar fp32 stores: NLD=1009 odd (alignment), plus P_ guard
                size_t o0 = (size_t)row * NLD + col;
                size_t o1 = (size_t)(row + 8) * NLD + col;
                if (col < P_)     { Cf[o0]     = v00; Cf[o1]     = v10; }
                if (col + 1 < P_) { Cf[o0 + 1] = v01; Cf[o1 + 1] = v11; }
            } else {
                *reinterpret_cast<uint32_t*>(Ch + (size_t)row * NLD + col)       = packh(v00, v01);
                *reinterpret_cast<uint32_t*>(Ch + (size_t)(row + 8) * NLD + col) = packh(v10, v11);
            }
        }
    }
}

// ---------------- launcher ----------------
extern "C" void kernel_launch(void* const* d_in, const int* in_sizes, int n_in,
                              void* d_out, int out_size) {
    const int*   x    = (const int*)d_in[0];
    const float* tok  = (const float*)d_in[1];
    const float* pos  = (const float*)d_in[2];
    const float* WQ   = (const float*)d_in[3];
    const float* WK   = (const float*)d_in[4];
    const float* WV   = (const float*)d_in[5];
    const float* WO   = (const float*)d_in[6];
    const float* bQ   = (const float*)d_in[7];
    const float* bK   = (const float*)d_in[8];
    const float* bV   = (const float*)d_in[9];
    const float* bO   = (const float*)d_in[10];
    const float* fc1w = (const float*)d_in[11];
    const float* fc1b = (const float*)d_in[12];
    const float* fc2w = (const float*)d_in[13];
    const float* fc2b = (const float*)d_in[14];
    const float* unw  = (const float*)d_in[15];
    const float* unb  = (const float*)d_in[16];
    float* out = (float*)d_out;

    cudaFuncSetAttribute(gemm_h<0>, cudaFuncAttributeMaxDynamicSharedMemorySize, SMEM_T);
    cudaFuncSetAttribute(gemm_h<1>, cudaFuncAttributeMaxDynamicSharedMemorySize, SMEM_T);
    cudaFuncSetAttribute(gemm_h<2>, cudaFuncAttributeMaxDynamicSharedMemorySize, SMEM_T);

    pk_qkv <<<253,  256>>>(tok, pos, WQ, WK, WV, bQ, bK, bV);
    pk_m1  <<<256,  256>>>(WO, fc1w);
    pk_b1  <<<4,    256>>>(bO, fc1w, fc1b);
    pk_copy<<<1024, 256>>>(unw, unb, fc2w);
    attn_k <<<8192, 256>>>(x);

    gemm_h<0><<<dim3(8, 1024), 256, SMEM_T>>>(nullptr, nullptr);   // z -> hid
    gemm_h<1><<<dim3(2, 1024), 256, SMEM_T>>>(fc2b,    nullptr);   // hid -> resid
    gemm_h<2><<<dim3(8, 1024), 256, SMEM_T>>>(nullptr, out);       // resid -> logits
}